// round 2
// baseline (speedup 1.0000x reference)
#include <cuda_runtime.h>

#define BB 4
#define TT 2048
#define SS 2048
#define CC 1024
#define HH 16
#define DD 64
#define SCALE_F 0.125f

typedef unsigned long long u64;

__device__ __forceinline__ u64 pack2(float lo, float hi) {
    u64 r; asm("mov.b64 %0,{%1,%2};" : "=l"(r) : "f"(lo), "f"(hi)); return r;
}
__device__ __forceinline__ void unpack2(u64 v, float& lo, float& hi) {
    asm("mov.b64 {%0,%1},%2;" : "=f"(lo), "=f"(hi) : "l"(v));
}
__device__ __forceinline__ u64 ffma2(u64 a, u64 b, u64 c) {
    u64 d; asm("fma.rn.f32x2 %0,%1,%2,%3;" : "=l"(d) : "l"(a), "l"(b), "l"(c)); return d;
}
__device__ __forceinline__ u64 fmul2(u64 a, u64 b) {
    u64 d; asm("mul.rn.f32x2 %0,%1,%2;" : "=l"(d) : "l"(a), "l"(b)); return d;
}

// Scratch (allocation-free rule: __device__ globals)
__device__ float g_q[BB * HH * TT * DD];     // (B,H,T,D)
__device__ float g_k[BB * HH * SS * DD];     // (B,H,S,D)
__device__ float g_v[BB * HH * SS * DD];     // (B,H,S,D)
__device__ float g_attn[BB * TT * CC];       // (B,T,H*D)

// ---------------------------------------------------------------------------
// GEMM: out = A[M,K] @ W[N,K]^T + bias.
// MODE 0: out row-major (M,N).  MODE 1: scatter to (B,H,T,D) with m=b*T+t, n=h*D+d.
// 128x128 block tile, TK=16, 256 threads, 8x8 per thread, f32x2-packed FMAs.
// ---------------------------------------------------------------------------
template <int MODE>
__global__ __launch_bounds__(256) void gemm_kernel(
    const float* __restrict__ A, const float* __restrict__ W,
    const float* __restrict__ bias, float* __restrict__ out,
    int M, int N, int K)
{
    constexpr int TM = 128, TN = 128, TK = 16;
    __shared__ __align__(16) float As[TK][TM + 4];
    __shared__ __align__(16) float Bs[TK][TN + 4];

    const int tid = threadIdx.x;
    const int tx = tid & 15, ty = tid >> 4;
    const int bm = blockIdx.y * TM, bn = blockIdx.x * TN;

    u64 acc[8][4];
#pragma unroll
    for (int i = 0; i < 8; i++)
#pragma unroll
        for (int j = 0; j < 4; j++) acc[i][j] = 0ull;

    const float* Aptr = A + (size_t)bm * K;
    const float* Wptr = W + (size_t)bn * K;

    for (int k0 = 0; k0 < K; k0 += TK) {
#pragma unroll
        for (int i = 0; i < 2; i++) {
            int c = tid + i * 256;            // 0..511 float4 slots
            int m = c >> 2, kg = (c & 3) << 2;
            float4 va = *(const float4*)(Aptr + (size_t)m * K + k0 + kg);
            As[kg + 0][m] = va.x; As[kg + 1][m] = va.y;
            As[kg + 2][m] = va.z; As[kg + 3][m] = va.w;
            float4 vb = *(const float4*)(Wptr + (size_t)m * K + k0 + kg);
            Bs[kg + 0][m] = vb.x; Bs[kg + 1][m] = vb.y;
            Bs[kg + 2][m] = vb.z; Bs[kg + 3][m] = vb.w;
        }
        __syncthreads();
#pragma unroll
        for (int kk = 0; kk < TK; kk++) {
            float4 a0 = *(const float4*)&As[kk][ty * 8];
            float4 a1 = *(const float4*)&As[kk][ty * 8 + 4];
            const u64* bp = (const u64*)&Bs[kk][tx * 8];
            u64 b0 = bp[0], b1 = bp[1], b2 = bp[2], b3 = bp[3];
            float av[8] = {a0.x, a0.y, a0.z, a0.w, a1.x, a1.y, a1.z, a1.w};
#pragma unroll
            for (int i = 0; i < 8; i++) {
                u64 ab = pack2(av[i], av[i]);
                acc[i][0] = ffma2(ab, b0, acc[i][0]);
                acc[i][1] = ffma2(ab, b1, acc[i][1]);
                acc[i][2] = ffma2(ab, b2, acc[i][2]);
                acc[i][3] = ffma2(ab, b3, acc[i][3]);
            }
        }
        __syncthreads();
    }

#pragma unroll
    for (int i = 0; i < 8; i++) {
        int m = bm + ty * 8 + i;
#pragma unroll
        for (int j = 0; j < 4; j++) {
            float lo, hi;
            unpack2(acc[i][j], lo, hi);
            int n0 = bn + tx * 8 + j * 2;
            float v0 = lo + bias[n0];
            float v1 = hi + bias[n0 + 1];
            if (MODE == 0) {
                float* p = out + (size_t)m * N + n0;
                p[0] = v0; p[1] = v1;
            } else {
                int b_ = m >> 11, t = m & (TT - 1);
                int h = n0 >> 6, d = n0 & (DD - 1);
                float* p = out + (((size_t)b_ * HH + h) * TT + t) * DD + d;
                p[0] = v0; p[1] = v1;
            }
        }
    }
}

// ---------------------------------------------------------------------------
// Flash attention: per (b, h, 128-row T tile), stream S in 64-wide tiles.
// 256 threads as 16x16 grid; thread (tx,ty) owns S rows ty*8..+7.
// Q,K stored d-major in smem (conflict-free); online softmax in registers.
// ---------------------------------------------------------------------------
#define ATTN_SMEM_FLOATS (DD * 132 + DD * 66 + 64 * 68 + 128 * 68 + 64)
#define ATTN_SMEM_BYTES (ATTN_SMEM_FLOATS * 4)

__global__ __launch_bounds__(256) void attn_kernel(
    const float* __restrict__ mask, const unsigned char* __restrict__ kpm)
{
    extern __shared__ __align__(16) float sm[];
    float* Qs = sm;                       // [DD][132]  (d-major, t cols)
    float* Ks = Qs + DD * 132;            // [DD][66]   (d-major, s cols)
    float* Vs = Ks + DD * 66;             // [64][68]   (s rows, d cols)
    float* Ps = Vs + 64 * 68;             // [128][68]  (t rows, s cols)
    float* kpms = Ps + 128 * 68;          // [64]

    const int tid = threadIdx.x;
    const int tx = tid & 15, ty = tid >> 4;
    const int tblk = blockIdx.x * 128;
    const int h = blockIdx.y, b = blockIdx.z;
    const size_t base = ((size_t)b * HH + h) * (size_t)TT * DD;
    const float NEGINF = __int_as_float(0xff800000);

    {   // load Q tile (128 x 64), store transposed
        const float* qp = g_q + base + (size_t)tblk * DD;
#pragma unroll
        for (int i = 0; i < 8; i++) {
            int c = tid + i * 256;          // 0..2047 float4 slots
            int t = c >> 4, dg = (c & 15) << 2;
            float4 v = *(const float4*)(qp + t * DD + dg);
            Qs[(dg + 0) * 132 + t] = v.x;
            Qs[(dg + 1) * 132 + t] = v.y;
            Qs[(dg + 2) * 132 + t] = v.z;
            Qs[(dg + 3) * 132 + t] = v.w;
        }
    }

    float m_i[8], l_i[8];
    u64 o0[8], o1[8];
#pragma unroll
    for (int i = 0; i < 8; i++) { m_i[i] = NEGINF; l_i[i] = 0.f; o0[i] = 0ull; o1[i] = 0ull; }

    for (int s0 = 0; s0 < SS; s0 += 64) {
        const float* kp = g_k + base + (size_t)s0 * DD;
        const float* vp = g_v + base + (size_t)s0 * DD;
#pragma unroll
        for (int i = 0; i < 4; i++) {
            int c = tid + i * 256;          // 0..1023 float4 slots
            int s = c >> 4, dg = (c & 15) << 2;
            float4 kv = *(const float4*)(kp + s * DD + dg);
            Ks[(dg + 0) * 66 + s] = kv.x;
            Ks[(dg + 1) * 66 + s] = kv.y;
            Ks[(dg + 2) * 66 + s] = kv.z;
            Ks[(dg + 3) * 66 + s] = kv.w;
            float4 vv = *(const float4*)(vp + s * DD + dg);
            *(float4*)&Vs[s * 68 + dg] = vv;
        }
        if (tid < 64) kpms[tid] = kpm[(size_t)b * SS + s0 + tid] ? NEGINF : 0.f;
        __syncthreads();

        // S = Q @ K^T : rows ty*8..+7, cols tx*4..+3 (packed pairs)
        u64 sa[8], sb[8];
#pragma unroll
        for (int i = 0; i < 8; i++) { sa[i] = 0ull; sb[i] = 0ull; }
#pragma unroll 8
        for (int d = 0; d < DD; d++) {
            float4 a0 = *(const float4*)&Qs[d * 132 + ty * 8];
            float4 a1 = *(const float4*)&Qs[d * 132 + ty * 8 + 4];
            u64 k0 = *(const u64*)&Ks[d * 66 + tx * 4];
            u64 k1 = *(const u64*)&Ks[d * 66 + tx * 4 + 2];
            float av[8] = {a0.x, a0.y, a0.z, a0.w, a1.x, a1.y, a1.z, a1.w};
#pragma unroll
            for (int i = 0; i < 8; i++) {
                u64 ab = pack2(av[i], av[i]);
                sa[i] = ffma2(ab, k0, sa[i]);
                sb[i] = ffma2(ab, k1, sb[i]);
            }
        }

        // online softmax per row (row reduction over 16 lanes of half-warp)
#pragma unroll
        for (int i = 0; i < 8; i++) {
            int tg = tblk + ty * 8 + i;
            float4 mv = *(const float4*)(mask + (size_t)tg * SS + s0 + tx * 4);
            float s0v, s1v, s2v, s3v;
            unpack2(sa[i], s0v, s1v);
            unpack2(sb[i], s2v, s3v);
            s0v = fmaf(s0v, SCALE_F, mv.x) + kpms[tx * 4 + 0];
            s1v = fmaf(s1v, SCALE_F, mv.y) + kpms[tx * 4 + 1];
            s2v = fmaf(s2v, SCALE_F, mv.z) + kpms[tx * 4 + 2];
            s3v = fmaf(s3v, SCALE_F, mv.w) + kpms[tx * 4 + 3];
            float mx = fmaxf(fmaxf(s0v, s1v), fmaxf(s2v, s3v));
#pragma unroll
            for (int off = 8; off; off >>= 1)
                mx = fmaxf(mx, __shfl_xor_sync(0xffffffffu, mx, off));
            float mnew = fmaxf(m_i[i], mx);
            float corr = __expf(m_i[i] - mnew);
            m_i[i] = mnew;
            float p0 = __expf(s0v - mnew);
            float p1 = __expf(s1v - mnew);
            float p2 = __expf(s2v - mnew);
            float p3 = __expf(s3v - mnew);
            float ps = (p0 + p1) + (p2 + p3);
#pragma unroll
            for (int off = 8; off; off >>= 1)
                ps += __shfl_xor_sync(0xffffffffu, ps, off);
            l_i[i] = l_i[i] * corr + ps;
            u64 c2 = pack2(corr, corr);
            o0[i] = fmul2(o0[i], c2);
            o1[i] = fmul2(o1[i], c2);
            *(float4*)&Ps[(ty * 8 + i) * 68 + tx * 4] = make_float4(p0, p1, p2, p3);
        }
        __syncthreads();

        // O += P @ V : rows ty*8..+7, d cols tx*4..+3 (packed pairs)
#pragma unroll 8
        for (int s = 0; s < 64; s++) {
            u64 v0 = *(const u64*)&Vs[s * 68 + tx * 4];
            u64 v1 = *(const u64*)&Vs[s * 68 + tx * 4 + 2];
#pragma unroll
            for (int i = 0; i < 8; i++) {
                float p = Ps[(ty * 8 + i) * 68 + s];
                u64 pb = pack2(p, p);
                o0[i] = ffma2(pb, v0, o0[i]);
                o1[i] = ffma2(pb, v1, o1[i]);
            }
        }
        __syncthreads();
    }

    // finalize: O /= l, write to (B, T, H*D)
#pragma unroll
    for (int i = 0; i < 8; i++) {
        float inv = __fdividef(1.f, l_i[i]);
        float a, bvv, c, d2;
        unpack2(o0[i], a, bvv);
        unpack2(o1[i], c, d2);
        int t = tblk + ty * 8 + i;
        float* op = g_attn + ((size_t)b * TT + t) * CC + h * DD + tx * 4;
        *(float4*)op = make_float4(a * inv, bvv * inv, c * inv, d2 * inv);
    }
}

// ---------------------------------------------------------------------------
// Launch
// ---------------------------------------------------------------------------
extern "C" void kernel_launch(void* const* d_in, const int* in_sizes, int n_in,
                              void* d_out, int out_size)
{
    (void)in_sizes; (void)n_in; (void)out_size;
    const float* query = (const float*)d_in[0];
    const float* key   = (const float*)d_in[1];
    const float* value = (const float*)d_in[2];
    const float* mask  = (const float*)d_in[3];
    const unsigned char* kpm = (const unsigned char*)d_in[4];
    const float* Wq = (const float*)d_in[5];
    const float* bq = (const float*)d_in[6];
    const float* Wk = (const float*)d_in[7];
    const float* bk = (const float*)d_in[8];
    const float* Wv = (const float*)d_in[9];
    const float* bv = (const float*)d_in[10];
    const float* Wout = (const float*)d_in[11];
    const float* bout = (const float*)d_in[12];
    float* out = (float*)d_out;

    float *qp, *kp, *vp, *ap;
    cudaGetSymbolAddress((void**)&qp, g_q);
    cudaGetSymbolAddress((void**)&kp, g_k);
    cudaGetSymbolAddress((void**)&vp, g_v);
    cudaGetSymbolAddress((void**)&ap, g_attn);

    dim3 ggrid(CC / 128, (BB * TT) / 128);   // (8, 64)
    gemm_kernel<1><<<ggrid, 256>>>(query, Wq, bq, qp, BB * TT, CC, CC);
    gemm_kernel<1><<<ggrid, 256>>>(key,   Wk, bk, kp, BB * SS, CC, CC);
    gemm_kernel<1><<<ggrid, 256>>>(value, Wv, bv, vp, BB * SS, CC, CC);

    cudaFuncSetAttribute(attn_kernel, cudaFuncAttributeMaxDynamicSharedMemorySize,
                         ATTN_SMEM_BYTES);
    attn_kernel<<<dim3(TT / 128, HH, BB), 256, ATTN_SMEM_BYTES>>>(mask, kpm);

    gemm_kernel<0><<<ggrid, 256>>>(ap, Wout, bout, out, BB * TT, CC, CC);
}

// round 4
// speedup vs baseline: 1.5266x; 1.5266x over previous
#include <cuda_runtime.h>
#include <cstdint>

#define BB 4
#define TT 2048
#define SS 2048
#define CC 1024
#define HH 16
#define DD 64
#define SCALE_F 0.125f

typedef unsigned long long u64;
typedef unsigned int u32;

__device__ __forceinline__ u64 pack2(float lo, float hi) {
    u64 r; asm("mov.b64 %0,{%1,%2};" : "=l"(r) : "f"(lo), "f"(hi)); return r;
}
__device__ __forceinline__ void unpack2(u64 v, float& lo, float& hi) {
    asm("mov.b64 {%0,%1},%2;" : "=f"(lo), "=f"(hi) : "l"(v));
}
__device__ __forceinline__ u64 ffma2(u64 a, u64 b, u64 c) {
    u64 d; asm("fma.rn.f32x2 %0,%1,%2,%3;" : "=l"(d) : "l"(a), "l"(b), "l"(c)); return d;
}
__device__ __forceinline__ u64 fmul2(u64 a, u64 b) {
    u64 d; asm("mul.rn.f32x2 %0,%1,%2;" : "=l"(d) : "l"(a), "l"(b)); return d;
}

// Scratch (allocation-free rule: __device__ globals)
__device__ float g_q[BB * HH * TT * DD];     // (B,H,T,D)
__device__ float g_k[BB * HH * SS * DD];     // (B,H,S,D)
__device__ float g_v[BB * HH * SS * DD];     // (B,H,S,D)
__device__ float g_attn[BB * TT * CC];       // (B,T,H*D)

__device__ __forceinline__ u32 smem_u32(const void* p) {
    u32 a;
    asm("{ .reg .u64 t; cvta.to.shared.u64 t, %1; cvt.u32.u64 %0, t; }" : "=r"(a) : "l"(p));
    return a;
}
__device__ __forceinline__ void ldsm4(u32 addr, u32& r0, u32& r1, u32& r2, u32& r3) {
    asm volatile("ldmatrix.sync.aligned.m8n8.x4.shared.b16 {%0,%1,%2,%3},[%4];"
                 : "=r"(r0), "=r"(r1), "=r"(r2), "=r"(r3) : "r"(addr));
}
__device__ __forceinline__ void mma16816(float* c, const u32* a, const u32* b) {
    asm volatile(
        "mma.sync.aligned.m16n8k16.row.col.f32.bf16.bf16.f32 "
        "{%0,%1,%2,%3},{%4,%5,%6,%7},{%8,%9},{%0,%1,%2,%3};"
        : "+f"(c[0]), "+f"(c[1]), "+f"(c[2]), "+f"(c[3])
        : "r"(a[0]), "r"(a[1]), "r"(a[2]), "r"(a[3]), "r"(b[0]), "r"(b[1]));
}

// ---------------------------------------------------------------------------
// Tensor-core GEMM: out = A[M,K] @ W[N,K]^T + bias, bf16x3 split emulation.
// MODE 0: row-major (M,N).  MODE 1: scatter to (B,H,T,D).
// 128x128 CTA tile, K in 64-wide chunks, single smem buffer, 2 CTAs/SM.
// smem: 4 tiles of [128][72] bf16 (row stride 144B): Ahi, Alo, Bhi, Blo.
// ---------------------------------------------------------------------------
#define TILE_B (128 * 144)               // 18432 bytes per tile
#define GEMM_SMEM_BYTES (4 * TILE_B)     // 73728

__device__ __forceinline__ void cvt_split_store(char* hi_tile, char* lo_tile,
                                                int r, int kq, float4 a) {
    u32 a0 = __float_as_uint(a.x), a1 = __float_as_uint(a.y);
    u32 a2 = __float_as_uint(a.z), a3 = __float_as_uint(a.w);
    u32 h01, h23;
    asm("prmt.b32 %0,%1,%2,0x7632;" : "=r"(h01) : "r"(a0), "r"(a1));
    asm("prmt.b32 %0,%1,%2,0x7632;" : "=r"(h23) : "r"(a2), "r"(a3));
    float l0 = a.x - __uint_as_float(a0 & 0xffff0000u);
    float l1 = a.y - __uint_as_float(a1 & 0xffff0000u);
    float l2 = a.z - __uint_as_float(a2 & 0xffff0000u);
    float l3 = a.w - __uint_as_float(a3 & 0xffff0000u);
    u32 lo01, lo23;
    asm("cvt.rn.bf16x2.f32 %0,%1,%2;" : "=r"(lo01) : "f"(l1), "f"(l0));
    asm("cvt.rn.bf16x2.f32 %0,%1,%2;" : "=r"(lo23) : "f"(l3), "f"(l2));
    u32 boff = (u32)(r * 144 + kq * 2);
    *(uint2*)(hi_tile + boff) = make_uint2(h01, h23);
    *(uint2*)(lo_tile + boff) = make_uint2(lo01, lo23);
}

template <int MODE>
__global__ __launch_bounds__(256, 2) void tc_gemm(
    const float* __restrict__ A, const float* __restrict__ W,
    const float* __restrict__ bias, float* __restrict__ out,
    int M, int N, int K)
{
    extern __shared__ __align__(128) char dsm[];
    char* Ahi = dsm;
    char* Alo = dsm + TILE_B;
    char* Bhi = dsm + 2 * TILE_B;
    char* Blo = dsm + 3 * TILE_B;
    const u32 sbase = smem_u32(dsm);

    const int tid = threadIdx.x;
    const int lane = tid & 31;
    const int wid = tid >> 5;
    const int wm = wid & 3;              // 4 warps along m (32 rows each)
    const int wn = wid >> 2;             // 2 warps along n (64 cols each)
    const int bm = blockIdx.y * 128, bn = blockIdx.x * 128;

    // ldmatrix lane address offsets (bytes, within a tile)
    // A: lanes 0-15 -> rows m0+l @k0, lanes 16-31 -> rows @k0+8
    const u32 aOff = (u32)((wm * 32 + (lane & 15)) * 144 + (lane >> 4) * 16);
    // B x4 covering 16 n-rows x 16 k
    const u32 bRow = (u32)(((lane >> 4) << 3) + (lane & 7));
    const u32 bOff = (u32)((wn * 64 + bRow) * 144 + ((lane >> 3) & 1) * 16);

    float acc[2][8][4];
#pragma unroll
    for (int i = 0; i < 2; i++)
#pragma unroll
        for (int j = 0; j < 8; j++)
#pragma unroll
            for (int q = 0; q < 4; q++) acc[i][j][q] = 0.f;

    const float* Ap = A + (size_t)bm * K;
    const float* Wp = W + (size_t)bn * K;

    const int nchunk = K / 64;
    for (int c = 0; c < nchunk; c++) {
        const int k0 = c * 64;
#pragma unroll
        for (int i = 0; i < 8; i++) {
            int f = tid + i * 256;                 // 0..2047 float4 slots
            int r = f >> 4, kq = (f & 15) << 2;
            float4 a = __ldg((const float4*)(Ap + (size_t)r * K + k0 + kq));
            cvt_split_store(Ahi, Alo, r, kq, a);
            float4 w = __ldg((const float4*)(Wp + (size_t)r * K + k0 + kq));
            cvt_split_store(Bhi, Blo, r, kq, w);
        }
        __syncthreads();

        const u32 aHiA = sbase + aOff;
        const u32 aLoA = aHiA + TILE_B;
        const u32 bHiA = sbase + 2 * TILE_B + bOff;
        const u32 bLoA = bHiA + TILE_B;
#pragma unroll
        for (int ks = 0; ks < 4; ks++) {
            u32 ah[2][4], al[2][4];
#pragma unroll
            for (int mf = 0; mf < 2; mf++) {
                ldsm4(aHiA + mf * 2304 + ks * 32, ah[mf][0], ah[mf][1], ah[mf][2], ah[mf][3]);
                ldsm4(aLoA + mf * 2304 + ks * 32, al[mf][0], al[mf][1], al[mf][2], al[mf][3]);
            }
#pragma unroll
            for (int ng = 0; ng < 4; ng++) {       // 16 n-cols per group
                u32 bh[4], bl[4];
                ldsm4(bHiA + ng * 2304 + ks * 32, bh[0], bh[1], bh[2], bh[3]);
                ldsm4(bLoA + ng * 2304 + ks * 32, bl[0], bl[1], bl[2], bl[3]);
#pragma unroll
                for (int half = 0; half < 2; half++) {
                    const u32* bhp = &bh[half * 2];
                    const u32* blp = &bl[half * 2];
                    int nf = ng * 2 + half;
#pragma unroll
                    for (int mf = 0; mf < 2; mf++) {
                        mma16816(acc[mf][nf], ah[mf], bhp);
                        mma16816(acc[mf][nf], ah[mf], blp);
                        mma16816(acc[mf][nf], al[mf], bhp);
                    }
                }
            }
        }
        __syncthreads();
    }

    // epilogue: acc lane mapping (m16n8): c0,c1 -> row l/4, cols (l&3)*2,+1; c2,c3 -> row+8
#pragma unroll
    for (int mf = 0; mf < 2; mf++) {
#pragma unroll
        for (int nf = 0; nf < 8; nf++) {
            int m = bm + wm * 32 + mf * 16 + (lane >> 2);
            int n = bn + wn * 64 + nf * 8 + (lane & 3) * 2;
            float b0 = __ldg(bias + n), b1 = __ldg(bias + n + 1);
            float2 v0 = make_float2(acc[mf][nf][0] + b0, acc[mf][nf][1] + b1);
            float2 v1 = make_float2(acc[mf][nf][2] + b0, acc[mf][nf][3] + b1);
            if (MODE == 0) {
                *(float2*)(out + (size_t)m * N + n) = v0;
                *(float2*)(out + (size_t)(m + 8) * N + n) = v1;
            } else {
                int h = n >> 6, d = n & (DD - 1);
                int b_ = m >> 11, t = m & (TT - 1);
                size_t idx0 = (((size_t)b_ * HH + h) * TT + t) * DD + d;
                *(float2*)(out + idx0) = v0;
                int m1 = m + 8;
                int b1_ = m1 >> 11, t1 = m1 & (TT - 1);
                size_t idx1 = (((size_t)b1_ * HH + h) * TT + t1) * DD + d;
                *(float2*)(out + idx1) = v1;
            }
        }
    }
}

// ---------------------------------------------------------------------------
// Flash attention (unchanged, passing at rel_err 1.3e-6)
// ---------------------------------------------------------------------------
#define ATTN_SMEM_FLOATS (DD * 132 + DD * 66 + 64 * 68 + 128 * 68 + 64)
#define ATTN_SMEM_BYTES (ATTN_SMEM_FLOATS * 4)

__global__ __launch_bounds__(256) void attn_kernel(
    const float* __restrict__ mask, const unsigned char* __restrict__ kpm)
{
    extern __shared__ __align__(16) float sm[];
    float* Qs = sm;                       // [DD][132]
    float* Ks = Qs + DD * 132;            // [DD][66]
    float* Vs = Ks + DD * 66;             // [64][68]
    float* Ps = Vs + 64 * 68;             // [128][68]
    float* kpms = Ps + 128 * 68;          // [64]

    const int tid = threadIdx.x;
    const int tx = tid & 15, ty = tid >> 4;
    const int tblk = blockIdx.x * 128;
    const int h = blockIdx.y, b = blockIdx.z;
    const size_t base = ((size_t)b * HH + h) * (size_t)TT * DD;
    const float NEGINF = __int_as_float(0xff800000);

    {
        const float* qp = g_q + base + (size_t)tblk * DD;
#pragma unroll
        for (int i = 0; i < 8; i++) {
            int c = tid + i * 256;
            int t = c >> 4, dg = (c & 15) << 2;
            float4 v = *(const float4*)(qp + t * DD + dg);
            Qs[(dg + 0) * 132 + t] = v.x;
            Qs[(dg + 1) * 132 + t] = v.y;
            Qs[(dg + 2) * 132 + t] = v.z;
            Qs[(dg + 3) * 132 + t] = v.w;
        }
    }

    float m_i[8], l_i[8];
    u64 o0[8], o1[8];
#pragma unroll
    for (int i = 0; i < 8; i++) { m_i[i] = NEGINF; l_i[i] = 0.f; o0[i] = 0ull; o1[i] = 0ull; }

    for (int s0 = 0; s0 < SS; s0 += 64) {
        const float* kp = g_k + base + (size_t)s0 * DD;
        const float* vp = g_v + base + (size_t)s0 * DD;
#pragma unroll
        for (int i = 0; i < 4; i++) {
            int c = tid + i * 256;
            int s = c >> 4, dg = (c & 15) << 2;
            float4 kv = *(const float4*)(kp + s * DD + dg);
            Ks[(dg + 0) * 66 + s] = kv.x;
            Ks[(dg + 1) * 66 + s] = kv.y;
            Ks[(dg + 2) * 66 + s] = kv.z;
            Ks[(dg + 3) * 66 + s] = kv.w;
            float4 vv = *(const float4*)(vp + s * DD + dg);
            *(float4*)&Vs[s * 68 + dg] = vv;
        }
        if (tid < 64) kpms[tid] = kpm[(size_t)b * SS + s0 + tid] ? NEGINF : 0.f;
        __syncthreads();

        u64 sa[8], sb[8];
#pragma unroll
        for (int i = 0; i < 8; i++) { sa[i] = 0ull; sb[i] = 0ull; }
#pragma unroll 8
        for (int d = 0; d < DD; d++) {
            float4 a0 = *(const float4*)&Qs[d * 132 + ty * 8];
            float4 a1 = *(const float4*)&Qs[d * 132 + ty * 8 + 4];
            u64 k0 = *(const u64*)&Ks[d * 66 + tx * 4];
            u64 k1 = *(const u64*)&Ks[d * 66 + tx * 4 + 2];
            float av[8] = {a0.x, a0.y, a0.z, a0.w, a1.x, a1.y, a1.z, a1.w};
#pragma unroll
            for (int i = 0; i < 8; i++) {
                u64 ab = pack2(av[i], av[i]);
                sa[i] = ffma2(ab, k0, sa[i]);
                sb[i] = ffma2(ab, k1, sb[i]);
            }
        }

#pragma unroll
        for (int i = 0; i < 8; i++) {
            int tg = tblk + ty * 8 + i;
            float4 mv = *(const float4*)(mask + (size_t)tg * SS + s0 + tx * 4);
            float s0v, s1v, s2v, s3v;
            unpack2(sa[i], s0v, s1v);
            unpack2(sb[i], s2v, s3v);
            s0v = fmaf(s0v, SCALE_F, mv.x) + kpms[tx * 4 + 0];
            s1v = fmaf(s1v, SCALE_F, mv.y) + kpms[tx * 4 + 1];
            s2v = fmaf(s2v, SCALE_F, mv.z) + kpms[tx * 4 + 2];
            s3v = fmaf(s3v, SCALE_F, mv.w) + kpms[tx * 4 + 3];
            float mx = fmaxf(fmaxf(s0v, s1v), fmaxf(s2v, s3v));
#pragma unroll
            for (int off = 8; off; off >>= 1)
                mx = fmaxf(mx, __shfl_xor_sync(0xffffffffu, mx, off));
            float mnew = fmaxf(m_i[i], mx);
            float corr = __expf(m_i[i] - mnew);
            m_i[i] = mnew;
            float p0 = __expf(s0v - mnew);
            float p1 = __expf(s1v - mnew);
            float p2 = __expf(s2v - mnew);
            float p3 = __expf(s3v - mnew);
            float ps = (p0 + p1) + (p2 + p3);
#pragma unroll
            for (int off = 8; off; off >>= 1)
                ps += __shfl_xor_sync(0xffffffffu, ps, off);
            l_i[i] = l_i[i] * corr + ps;
            u64 c2 = pack2(corr, corr);
            o0[i] = fmul2(o0[i], c2);
            o1[i] = fmul2(o1[i], c2);
            *(float4*)&Ps[(ty * 8 + i) * 68 + tx * 4] = make_float4(p0, p1, p2, p3);
        }
        __syncthreads();

#pragma unroll 8
        for (int s = 0; s < 64; s++) {
            u64 v0 = *(const u64*)&Vs[s * 68 + tx * 4];
            u64 v1 = *(const u64*)&Vs[s * 68 + tx * 4 + 2];
#pragma unroll
            for (int i = 0; i < 8; i++) {
                float p = Ps[(ty * 8 + i) * 68 + s];
                u64 pb = pack2(p, p);
                o0[i] = ffma2(pb, v0, o0[i]);
                o1[i] = ffma2(pb, v1, o1[i]);
            }
        }
        __syncthreads();
    }

#pragma unroll
    for (int i = 0; i < 8; i++) {
        float inv = __fdividef(1.f, l_i[i]);
        float a, bvv, c, d2;
        unpack2(o0[i], a, bvv);
        unpack2(o1[i], c, d2);
        int t = tblk + ty * 8 + i;
        float* op = g_attn + ((size_t)b * TT + t) * CC + h * DD + tx * 4;
        *(float4*)op = make_float4(a * inv, bvv * inv, c * inv, d2 * inv);
    }
}

// ---------------------------------------------------------------------------
// Launch
// ---------------------------------------------------------------------------
extern "C" void kernel_launch(void* const* d_in, const int* in_sizes, int n_in,
                              void* d_out, int out_size)
{
    (void)in_sizes; (void)n_in; (void)out_size;
    const float* query = (const float*)d_in[0];
    const float* key   = (const float*)d_in[1];
    const float* value = (const float*)d_in[2];
    const float* mask  = (const float*)d_in[3];
    const unsigned char* kpm = (const unsigned char*)d_in[4];
    const float* Wq = (const float*)d_in[5];
    const float* bq = (const float*)d_in[6];
    const float* Wk = (const float*)d_in[7];
    const float* bk = (const float*)d_in[8];
    const float* Wv = (const float*)d_in[9];
    const float* bv = (const float*)d_in[10];
    const float* Wout = (const float*)d_in[11];
    const float* bout = (const float*)d_in[12];
    float* out = (float*)d_out;

    float *qp, *kp, *vp, *ap;
    cudaGetSymbolAddress((void**)&qp, g_q);
    cudaGetSymbolAddress((void**)&kp, g_k);
    cudaGetSymbolAddress((void**)&vp, g_v);
    cudaGetSymbolAddress((void**)&ap, g_attn);

    cudaFuncSetAttribute(tc_gemm<0>, cudaFuncAttributeMaxDynamicSharedMemorySize,
                         GEMM_SMEM_BYTES);
    cudaFuncSetAttribute(tc_gemm<1>, cudaFuncAttributeMaxDynamicSharedMemorySize,
                         GEMM_SMEM_BYTES);
    cudaFuncSetAttribute(attn_kernel, cudaFuncAttributeMaxDynamicSharedMemorySize,
                         ATTN_SMEM_BYTES);

    dim3 ggrid(CC / 128, (BB * TT) / 128);   // (8, 64)
    tc_gemm<1><<<ggrid, 256, GEMM_SMEM_BYTES>>>(query, Wq, bq, qp, BB * TT, CC, CC);
    tc_gemm<1><<<ggrid, 256, GEMM_SMEM_BYTES>>>(key,   Wk, bk, kp, BB * SS, CC, CC);
    tc_gemm<1><<<ggrid, 256, GEMM_SMEM_BYTES>>>(value, Wv, bv, vp, BB * SS, CC, CC);

    attn_kernel<<<dim3(TT / 128, HH, BB), 256, ATTN_SMEM_BYTES>>>(mask, kpm);

    tc_gemm<0><<<ggrid, 256, GEMM_SMEM_BYTES>>>(ap, Wout, bout, out, BB * TT, CC, CC);
}

// round 5
// speedup vs baseline: 2.6464x; 1.7335x over previous
#include <cuda_runtime.h>
#include <cuda_fp16.h>
#include <cstdint>

#define BB 4
#define TT 2048
#define SS 2048
#define CC 1024
#define HH 16
#define DD 64
#define SCALE_F 0.125f

typedef unsigned long long u64;
typedef unsigned int u32;

// Scratch (allocation-free rule: __device__ globals)
__device__ float g_q[BB * HH * TT * DD];     // (B,H,T,D)
__device__ float g_k[BB * HH * SS * DD];     // (B,H,S,D)
__device__ float g_v[BB * HH * SS * DD];     // (B,H,S,D)
__device__ float g_attn[BB * TT * CC];       // (B,T,H*D)

__device__ __forceinline__ u32 smem_u32(const void* p) {
    u32 a;
    asm("{ .reg .u64 t; cvta.to.shared.u64 t, %1; cvt.u32.u64 %0, t; }" : "=r"(a) : "l"(p));
    return a;
}
__device__ __forceinline__ void ldsm4(u32 addr, u32& r0, u32& r1, u32& r2, u32& r3) {
    asm volatile("ldmatrix.sync.aligned.m8n8.x4.shared.b16 {%0,%1,%2,%3},[%4];"
                 : "=r"(r0), "=r"(r1), "=r"(r2), "=r"(r3) : "r"(addr));
}
__device__ __forceinline__ void ldsm4t(u32 addr, u32& r0, u32& r1, u32& r2, u32& r3) {
    asm volatile("ldmatrix.sync.aligned.m8n8.x4.trans.shared.b16 {%0,%1,%2,%3},[%4];"
                 : "=r"(r0), "=r"(r1), "=r"(r2), "=r"(r3) : "r"(addr));
}
__device__ __forceinline__ void mma16816(float* c, const u32* a, const u32* b) {
    asm volatile(
        "mma.sync.aligned.m16n8k16.row.col.f32.bf16.bf16.f32 "
        "{%0,%1,%2,%3},{%4,%5,%6,%7},{%8,%9},{%0,%1,%2,%3};"
        : "+f"(c[0]), "+f"(c[1]), "+f"(c[2]), "+f"(c[3])
        : "r"(a[0]), "r"(a[1]), "r"(a[2]), "r"(a[3]), "r"(b[0]), "r"(b[1]));
}
__device__ __forceinline__ void mma16816h(float* c, const u32* a, const u32* b) {
    asm volatile(
        "mma.sync.aligned.m16n8k16.row.col.f32.f16.f16.f32 "
        "{%0,%1,%2,%3},{%4,%5,%6,%7},{%8,%9},{%0,%1,%2,%3};"
        : "+f"(c[0]), "+f"(c[1]), "+f"(c[2]), "+f"(c[3])
        : "r"(a[0]), "r"(a[1]), "r"(a[2]), "r"(a[3]), "r"(b[0]), "r"(b[1]));
}
// pack two f32 -> f16x2 (lo in low half)
__device__ __forceinline__ u32 f16pair(float lo, float hi) {
    u32 r; asm("cvt.rn.f16x2.f32 %0,%1,%2;" : "=r"(r) : "f"(hi), "f"(lo)); return r;
}
__device__ __forceinline__ void h2unpack(u32 v, float& lo, float& hi) {
    asm("{.reg .b16 l,h; mov.b32 {l,h}, %2; cvt.f32.f16 %0, l; cvt.f32.f16 %1, h;}"
        : "=f"(lo), "=f"(hi) : "r"(v));
}

// ---------------------------------------------------------------------------
// Tensor-core GEMM (unchanged from R4, validated): bf16x3 split emulation.
// ---------------------------------------------------------------------------
#define TILE_B (128 * 144)
#define GEMM_SMEM_BYTES (4 * TILE_B)

__device__ __forceinline__ void cvt_split_store(char* hi_tile, char* lo_tile,
                                                int r, int kq, float4 a) {
    u32 a0 = __float_as_uint(a.x), a1 = __float_as_uint(a.y);
    u32 a2 = __float_as_uint(a.z), a3 = __float_as_uint(a.w);
    u32 h01, h23;
    asm("prmt.b32 %0,%1,%2,0x7632;" : "=r"(h01) : "r"(a0), "r"(a1));
    asm("prmt.b32 %0,%1,%2,0x7632;" : "=r"(h23) : "r"(a2), "r"(a3));
    float l0 = a.x - __uint_as_float(a0 & 0xffff0000u);
    float l1 = a.y - __uint_as_float(a1 & 0xffff0000u);
    float l2 = a.z - __uint_as_float(a2 & 0xffff0000u);
    float l3 = a.w - __uint_as_float(a3 & 0xffff0000u);
    u32 lo01, lo23;
    asm("cvt.rn.bf16x2.f32 %0,%1,%2;" : "=r"(lo01) : "f"(l1), "f"(l0));
    asm("cvt.rn.bf16x2.f32 %0,%1,%2;" : "=r"(lo23) : "f"(l3), "f"(l2));
    u32 boff = (u32)(r * 144 + kq * 2);
    *(uint2*)(hi_tile + boff) = make_uint2(h01, h23);
    *(uint2*)(lo_tile + boff) = make_uint2(lo01, lo23);
}

template <int MODE>
__global__ __launch_bounds__(256, 2) void tc_gemm(
    const float* __restrict__ A, const float* __restrict__ W,
    const float* __restrict__ bias, float* __restrict__ out,
    int M, int N, int K)
{
    extern __shared__ __align__(128) char dsm[];
    char* Ahi = dsm;
    char* Alo = dsm + TILE_B;
    char* Bhi = dsm + 2 * TILE_B;
    char* Blo = dsm + 3 * TILE_B;
    const u32 sbase = smem_u32(dsm);

    const int tid = threadIdx.x;
    const int lane = tid & 31;
    const int wid = tid >> 5;
    const int wm = wid & 3;
    const int wn = wid >> 2;
    const int bm = blockIdx.y * 128, bn = blockIdx.x * 128;

    const u32 aOff = (u32)((wm * 32 + (lane & 15)) * 144 + (lane >> 4) * 16);
    const u32 bRow = (u32)(((lane >> 4) << 3) + (lane & 7));
    const u32 bOff = (u32)((wn * 64 + bRow) * 144 + ((lane >> 3) & 1) * 16);

    float acc[2][8][4];
#pragma unroll
    for (int i = 0; i < 2; i++)
#pragma unroll
        for (int j = 0; j < 8; j++)
#pragma unroll
            for (int q = 0; q < 4; q++) acc[i][j][q] = 0.f;

    const float* Ap = A + (size_t)bm * K;
    const float* Wp = W + (size_t)bn * K;

    const int nchunk = K / 64;
    for (int c = 0; c < nchunk; c++) {
        const int k0 = c * 64;
#pragma unroll
        for (int i = 0; i < 8; i++) {
            int f = tid + i * 256;
            int r = f >> 4, kq = (f & 15) << 2;
            float4 a = __ldg((const float4*)(Ap + (size_t)r * K + k0 + kq));
            cvt_split_store(Ahi, Alo, r, kq, a);
            float4 w = __ldg((const float4*)(Wp + (size_t)r * K + k0 + kq));
            cvt_split_store(Bhi, Blo, r, kq, w);
        }
        __syncthreads();

        const u32 aHiA = sbase + aOff;
        const u32 aLoA = aHiA + TILE_B;
        const u32 bHiA = sbase + 2 * TILE_B + bOff;
        const u32 bLoA = bHiA + TILE_B;
#pragma unroll
        for (int ks = 0; ks < 4; ks++) {
            u32 ah[2][4], al[2][4];
#pragma unroll
            for (int mf = 0; mf < 2; mf++) {
                ldsm4(aHiA + mf * 2304 + ks * 32, ah[mf][0], ah[mf][1], ah[mf][2], ah[mf][3]);
                ldsm4(aLoA + mf * 2304 + ks * 32, al[mf][0], al[mf][1], al[mf][2], al[mf][3]);
            }
#pragma unroll
            for (int ng = 0; ng < 4; ng++) {
                u32 bh[4], bl[4];
                ldsm4(bHiA + ng * 2304 + ks * 32, bh[0], bh[1], bh[2], bh[3]);
                ldsm4(bLoA + ng * 2304 + ks * 32, bl[0], bl[1], bl[2], bl[3]);
#pragma unroll
                for (int half = 0; half < 2; half++) {
                    const u32* bhp = &bh[half * 2];
                    const u32* blp = &bl[half * 2];
                    int nf = ng * 2 + half;
#pragma unroll
                    for (int mf = 0; mf < 2; mf++) {
                        mma16816(acc[mf][nf], ah[mf], bhp);
                        mma16816(acc[mf][nf], ah[mf], blp);
                        mma16816(acc[mf][nf], al[mf], bhp);
                    }
                }
            }
        }
        __syncthreads();
    }

#pragma unroll
    for (int mf = 0; mf < 2; mf++) {
#pragma unroll
        for (int nf = 0; nf < 8; nf++) {
            int m = bm + wm * 32 + mf * 16 + (lane >> 2);
            int n = bn + wn * 64 + nf * 8 + (lane & 3) * 2;
            float b0 = __ldg(bias + n), b1 = __ldg(bias + n + 1);
            float2 v0 = make_float2(acc[mf][nf][0] + b0, acc[mf][nf][1] + b1);
            float2 v1 = make_float2(acc[mf][nf][2] + b0, acc[mf][nf][3] + b1);
            if (MODE == 0) {
                *(float2*)(out + (size_t)m * N + n) = v0;
                *(float2*)(out + (size_t)(m + 8) * N + n) = v1;
            } else {
                int h = n >> 6, d = n & (DD - 1);
                int b_ = m >> 11, t = m & (TT - 1);
                size_t idx0 = (((size_t)b_ * HH + h) * TT + t) * DD + d;
                *(float2*)(out + idx0) = v0;
                int m1 = m + 8;
                int b1_ = m1 >> 11, t1 = m1 & (TT - 1);
                size_t idx1 = (((size_t)b1_ * HH + h) * TT + t1) * DD + d;
                *(float2*)(out + idx1) = v1;
            }
        }
    }
}

// ---------------------------------------------------------------------------
// Tensor-core flash attention.
// Grid (TT/128, HH, BB), 256 threads = 8 warps; warp w owns t-rows w*16..+15.
// S streamed in 64-wide chunks. f16 hi/lo split for Q,K,V and P (3-MMA each).
// smem layout (byte offsets, row stride 144B = 72 f16):
//   0      Qhi[128][72]   18432
//   18432  Qlo            18432
//   36864  Khi[64][72]     9216
//   46080  Klo             9216
//   55296  Vhi[64][72]     9216
//   64512  Vlo             9216
//   73728  kpms[2048] f32  8192
#define ATTN_SMEM_BYTES 81920
#define QLO_D 18432
#define KH_O 36864
#define KLO_D 9216
#define VH_O 55296
#define VLO_D 9216
#define KPM_O 73728

__device__ __forceinline__ void split_store_f16(char* hi_t, char* lo_t,
                                                int r, int kq, float4 a) {
    u32 h01 = f16pair(a.x, a.y);
    u32 h23 = f16pair(a.z, a.w);
    float bx, by, bz, bw;
    h2unpack(h01, bx, by);
    h2unpack(h23, bz, bw);
    u32 l01 = f16pair(a.x - bx, a.y - by);
    u32 l23 = f16pair(a.z - bz, a.w - bw);
    u32 off = (u32)(r * 144 + kq * 2);
    *(uint2*)(hi_t + off) = make_uint2(h01, h23);
    *(uint2*)(lo_t + off) = make_uint2(l01, l23);
}

__global__ __launch_bounds__(256, 2) void attn_tc(
    const float* __restrict__ mask, const unsigned char* __restrict__ kpm)
{
    extern __shared__ __align__(128) char smr[];
    float* kpms = (float*)(smr + KPM_O);
    const u32 sb = smem_u32(smr);

    const int tid = threadIdx.x;
    const int lane = tid & 31;
    const int w = tid >> 5;
    const int tblk = blockIdx.x * 128;
    const int h = blockIdx.y, b = blockIdx.z;
    const float NEGINF = __int_as_float(0xff800000);

    const size_t baseq = (((size_t)b * HH + h) * TT + tblk) * DD;
    const size_t basekv = ((size_t)b * HH + h) * (size_t)SS * DD;

    // Load + split Q tile (128 x 64)
#pragma unroll
    for (int i = 0; i < 8; i++) {
        int f = tid + i * 256;
        int r = f >> 4, kq = (f & 15) << 2;
        float4 v = *(const float4*)(g_q + baseq + (size_t)r * DD + kq);
        split_store_f16(smr, smr + QLO_D, r, kq, v);
    }
    // key-padding mask -> additive f32
#pragma unroll
    for (int i = 0; i < 8; i++) {
        int s = tid + i * 256;
        kpms[s] = kpm[(size_t)b * SS + s] ? NEGINF : 0.f;
    }

    // per-thread fragment addresses
    const u32 aQ = sb + (u32)((w * 16 + (lane & 15)) * 144 + (lane >> 4) * 16);
    const u32 bK = sb + KH_O + (u32)((((lane >> 4) << 3) + (lane & 7)) * 144 +
                                     ((lane >> 3) & 1) * 16);
    const u32 bV = sb + VH_O + (u32)((lane & 15) * 144 + (lane >> 4) * 16);

    const int row0 = tblk + w * 16 + (lane >> 2);
    const float* mrow0 = mask + (size_t)row0 * SS;
    const float* mrow1 = mrow0 + 8 * (size_t)SS;

    float O[8][4];
#pragma unroll
    for (int i = 0; i < 8; i++)
#pragma unroll
        for (int j = 0; j < 4; j++) O[i][j] = 0.f;
    float l0 = 0.f, l1 = 0.f, m0 = NEGINF, m1 = NEGINF;

    for (int s0 = 0; s0 < SS; s0 += 64) {
        __syncthreads();
        // load + split K,V chunk (64 x 64 each)
#pragma unroll
        for (int i = 0; i < 4; i++) {
            int f = tid + i * 256;
            int s = f >> 4, dg = (f & 15) << 2;
            float4 kv = *(const float4*)(g_k + basekv + (size_t)(s0 + s) * DD + dg);
            split_store_f16(smr + KH_O, smr + KH_O + KLO_D, s, dg, kv);
            float4 vv = *(const float4*)(g_v + basekv + (size_t)(s0 + s) * DD + dg);
            split_store_f16(smr + VH_O, smr + VH_O + VLO_D, s, dg, vv);
        }
        __syncthreads();

        // S = Q K^T  (f16 3-term split)
        float sacc[8][4];
#pragma unroll
        for (int i = 0; i < 8; i++)
#pragma unroll
            for (int j = 0; j < 4; j++) sacc[i][j] = 0.f;
#pragma unroll
        for (int ks = 0; ks < 4; ks++) {
            u32 ah[4], al[4];
            ldsm4(aQ + ks * 32, ah[0], ah[1], ah[2], ah[3]);
            ldsm4(aQ + QLO_D + ks * 32, al[0], al[1], al[2], al[3]);
#pragma unroll
            for (int sg = 0; sg < 4; sg++) {
                u32 bh[4], bl[4];
                ldsm4(bK + sg * 2304 + ks * 32, bh[0], bh[1], bh[2], bh[3]);
                ldsm4(bK + KLO_D + sg * 2304 + ks * 32, bl[0], bl[1], bl[2], bl[3]);
#pragma unroll
                for (int half = 0; half < 2; half++) {
                    float* c = sacc[sg * 2 + half];
                    mma16816h(c, ah, &bh[half * 2]);
                    mma16816h(c, ah, &bl[half * 2]);
                    mma16816h(c, al, &bh[half * 2]);
                }
            }
        }

        // mask + scale, row max
        float cm0 = NEGINF, cm1 = NEGINF;
#pragma unroll
        for (int nf = 0; nf < 8; nf++) {
            int col = s0 + nf * 8 + (lane & 3) * 2;
            float2 kp = *(const float2*)&kpms[col];
            float2 mv0 = __ldg((const float2*)(mrow0 + col));
            float2 mv1 = __ldg((const float2*)(mrow1 + col));
            sacc[nf][0] = fmaf(sacc[nf][0], SCALE_F, mv0.x + kp.x);
            sacc[nf][1] = fmaf(sacc[nf][1], SCALE_F, mv0.y + kp.y);
            sacc[nf][2] = fmaf(sacc[nf][2], SCALE_F, mv1.x + kp.x);
            sacc[nf][3] = fmaf(sacc[nf][3], SCALE_F, mv1.y + kp.y);
            cm0 = fmaxf(cm0, fmaxf(sacc[nf][0], sacc[nf][1]));
            cm1 = fmaxf(cm1, fmaxf(sacc[nf][2], sacc[nf][3]));
        }
        cm0 = fmaxf(cm0, __shfl_xor_sync(0xffffffffu, cm0, 1));
        cm0 = fmaxf(cm0, __shfl_xor_sync(0xffffffffu, cm0, 2));
        cm1 = fmaxf(cm1, __shfl_xor_sync(0xffffffffu, cm1, 1));
        cm1 = fmaxf(cm1, __shfl_xor_sync(0xffffffffu, cm1, 2));

        float mn0 = fmaxf(m0, cm0), mn1 = fmaxf(m1, cm1);
        float c0 = __expf(m0 - mn0), c1 = __expf(m1 - mn1);
        m0 = mn0; m1 = mn1;
        l0 *= c0; l1 *= c1;
#pragma unroll
        for (int nf = 0; nf < 8; nf++) {
            O[nf][0] *= c0; O[nf][1] *= c0;
            O[nf][2] *= c1; O[nf][3] *= c1;
        }

        // p = exp(s - m), split to f16 hi/lo; row sums
        u32 phi[8][2], plo[8][2];
        float rs0 = 0.f, rs1 = 0.f;
#pragma unroll
        for (int nf = 0; nf < 8; nf++) {
            float p0 = __expf(sacc[nf][0] - mn0);
            float p1 = __expf(sacc[nf][1] - mn0);
            float p2 = __expf(sacc[nf][2] - mn1);
            float p3 = __expf(sacc[nf][3] - mn1);
            rs0 += p0 + p1; rs1 += p2 + p3;
            phi[nf][0] = f16pair(p0, p1);
            phi[nf][1] = f16pair(p2, p3);
            float q0, q1, q2, q3;
            h2unpack(phi[nf][0], q0, q1);
            h2unpack(phi[nf][1], q2, q3);
            plo[nf][0] = f16pair(p0 - q0, p1 - q1);
            plo[nf][1] = f16pair(p2 - q2, p3 - q3);
        }
        rs0 += __shfl_xor_sync(0xffffffffu, rs0, 1);
        rs0 += __shfl_xor_sync(0xffffffffu, rs0, 2);
        rs1 += __shfl_xor_sync(0xffffffffu, rs1, 1);
        rs1 += __shfl_xor_sync(0xffffffffu, rs1, 2);
        l0 += rs0; l1 += rs1;

        // O += P V  (f16 3-term split); P frags direct from registers
#pragma unroll
        for (int ks = 0; ks < 4; ks++) {
            u32 ah[4] = {phi[2 * ks][0], phi[2 * ks][1],
                         phi[2 * ks + 1][0], phi[2 * ks + 1][1]};
            u32 al[4] = {plo[2 * ks][0], plo[2 * ks][1],
                         plo[2 * ks + 1][0], plo[2 * ks + 1][1]};
#pragma unroll
            for (int dg = 0; dg < 4; dg++) {
                u32 bh[4], bl[4];
                ldsm4t(bV + ks * 2304 + dg * 32, bh[0], bh[1], bh[2], bh[3]);
                ldsm4t(bV + VLO_D + ks * 2304 + dg * 32, bl[0], bl[1], bl[2], bl[3]);
                mma16816h(O[dg * 2], ah, &bh[0]);
                mma16816h(O[dg * 2], al, &bh[0]);
                mma16816h(O[dg * 2], ah, &bl[0]);
                mma16816h(O[dg * 2 + 1], ah, &bh[2]);
                mma16816h(O[dg * 2 + 1], al, &bh[2]);
                mma16816h(O[dg * 2 + 1], ah, &bl[2]);
            }
        }
    }

    // epilogue
    float i0 = __fdividef(1.f, l0), i1 = __fdividef(1.f, l1);
    float* op0 = g_attn + ((size_t)b * TT + row0) * CC + h * DD + (lane & 3) * 2;
    float* op1 = op0 + 8 * (size_t)CC;
#pragma unroll
    for (int nf = 0; nf < 8; nf++) {
        *(float2*)(op0 + nf * 8) = make_float2(O[nf][0] * i0, O[nf][1] * i0);
        *(float2*)(op1 + nf * 8) = make_float2(O[nf][2] * i1, O[nf][3] * i1);
    }
}

// ---------------------------------------------------------------------------
// Launch
// ---------------------------------------------------------------------------
extern "C" void kernel_launch(void* const* d_in, const int* in_sizes, int n_in,
                              void* d_out, int out_size)
{
    (void)in_sizes; (void)n_in; (void)out_size;
    const float* query = (const float*)d_in[0];
    const float* key   = (const float*)d_in[1];
    const float* value = (const float*)d_in[2];
    const float* mask  = (const float*)d_in[3];
    const unsigned char* kpm = (const unsigned char*)d_in[4];
    const float* Wq = (const float*)d_in[5];
    const float* bq = (const float*)d_in[6];
    const float* Wk = (const float*)d_in[7];
    const float* bk = (const float*)d_in[8];
    const float* Wv = (const float*)d_in[9];
    const float* bv = (const float*)d_in[10];
    const float* Wout = (const float*)d_in[11];
    const float* bout = (const float*)d_in[12];
    float* out = (float*)d_out;

    float *qp, *kp, *vp, *ap;
    cudaGetSymbolAddress((void**)&qp, g_q);
    cudaGetSymbolAddress((void**)&kp, g_k);
    cudaGetSymbolAddress((void**)&vp, g_v);
    cudaGetSymbolAddress((void**)&ap, g_attn);

    cudaFuncSetAttribute(tc_gemm<0>, cudaFuncAttributeMaxDynamicSharedMemorySize,
                         GEMM_SMEM_BYTES);
    cudaFuncSetAttribute(tc_gemm<1>, cudaFuncAttributeMaxDynamicSharedMemorySize,
                         GEMM_SMEM_BYTES);
    cudaFuncSetAttribute(attn_tc, cudaFuncAttributeMaxDynamicSharedMemorySize,
                         ATTN_SMEM_BYTES);

    dim3 ggrid(CC / 128, (BB * TT) / 128);   // (8, 64)
    tc_gemm<1><<<ggrid, 256, GEMM_SMEM_BYTES>>>(query, Wq, bq, qp, BB * TT, CC, CC);
    tc_gemm<1><<<ggrid, 256, GEMM_SMEM_BYTES>>>(key,   Wk, bk, kp, BB * SS, CC, CC);
    tc_gemm<1><<<ggrid, 256, GEMM_SMEM_BYTES>>>(value, Wv, bv, vp, BB * SS, CC, CC);

    attn_tc<<<dim3(TT / 128, HH, BB), 256, ATTN_SMEM_BYTES>>>(mask, kpm);

    tc_gemm<0><<<ggrid, 256, GEMM_SMEM_BYTES>>>(ap, Wout, bout, out, BB * TT, CC, CC);
}

// round 6
// speedup vs baseline: 2.9774x; 1.1251x over previous
#include <cuda_runtime.h>
#include <cuda_fp16.h>
#include <cstdint>

#define BB 4
#define TT 2048
#define SS 2048
#define CC 1024
#define HH 16
#define DD 64
#define SCALE_F 0.125f

typedef unsigned long long u64;
typedef unsigned int u32;

// Scratch (allocation-free rule: __device__ globals)
__device__ float g_q[BB * HH * TT * DD];     // (B,H,T,D)
__device__ float g_k[BB * HH * SS * DD];     // (B,H,S,D)
__device__ float g_v[BB * HH * SS * DD];     // (B,H,S,D)
__device__ float g_attn[BB * TT * CC];       // (B,T,H*D)
__device__ int   g_flags;                    // bit0: mask nonzero, bit1: kpm any

__device__ __forceinline__ u32 smem_u32(const void* p) {
    u32 a;
    asm("{ .reg .u64 t; cvta.to.shared.u64 t, %1; cvt.u32.u64 %0, t; }" : "=r"(a) : "l"(p));
    return a;
}
__device__ __forceinline__ void ldsm4(u32 addr, u32& r0, u32& r1, u32& r2, u32& r3) {
    asm volatile("ldmatrix.sync.aligned.m8n8.x4.shared.b16 {%0,%1,%2,%3},[%4];"
                 : "=r"(r0), "=r"(r1), "=r"(r2), "=r"(r3) : "r"(addr));
}
__device__ __forceinline__ void ldsm4t(u32 addr, u32& r0, u32& r1, u32& r2, u32& r3) {
    asm volatile("ldmatrix.sync.aligned.m8n8.x4.trans.shared.b16 {%0,%1,%2,%3},[%4];"
                 : "=r"(r0), "=r"(r1), "=r"(r2), "=r"(r3) : "r"(addr));
}
__device__ __forceinline__ void mma16816(float* c, const u32* a, const u32* b) {
    asm volatile(
        "mma.sync.aligned.m16n8k16.row.col.f32.bf16.bf16.f32 "
        "{%0,%1,%2,%3},{%4,%5,%6,%7},{%8,%9},{%0,%1,%2,%3};"
        : "+f"(c[0]), "+f"(c[1]), "+f"(c[2]), "+f"(c[3])
        : "r"(a[0]), "r"(a[1]), "r"(a[2]), "r"(a[3]), "r"(b[0]), "r"(b[1]));
}
__device__ __forceinline__ void mma16816h(float* c, const u32* a, const u32* b) {
    asm volatile(
        "mma.sync.aligned.m16n8k16.row.col.f32.f16.f16.f32 "
        "{%0,%1,%2,%3},{%4,%5,%6,%7},{%8,%9},{%0,%1,%2,%3};"
        : "+f"(c[0]), "+f"(c[1]), "+f"(c[2]), "+f"(c[3])
        : "r"(a[0]), "r"(a[1]), "r"(a[2]), "r"(a[3]), "r"(b[0]), "r"(b[1]));
}
__device__ __forceinline__ u32 f16pair(float lo, float hi) {
    u32 r; asm("cvt.rn.f16x2.f32 %0,%1,%2;" : "=r"(r) : "f"(hi), "f"(lo)); return r;
}
__device__ __forceinline__ void h2unpack(u32 v, float& lo, float& hi) {
    asm("{.reg .b16 l,h; mov.b32 {l,h}, %2; cvt.f32.f16 %0, l; cvt.f32.f16 %1, h;}"
        : "=f"(lo), "=f"(hi) : "r"(v));
}

// ---------------------------------------------------------------------------
// Mask content check: sets g_flags bit0 if attn_mask has any nonzero,
// bit1 if key_padding_mask has any true. g_flags zeroed via memset before.
// ---------------------------------------------------------------------------
__global__ void mask_check(const float* __restrict__ mask,
                           const unsigned char* __restrict__ kpm)
{
    int idx = blockIdx.x * blockDim.x + threadIdx.x;
    int stride = gridDim.x * blockDim.x;
    int any_m = 0;
    const float4* m4 = (const float4*)mask;
    for (int i = idx; i < (TT * SS) / 4; i += stride) {
        float4 v = __ldg(m4 + i);
        any_m |= (v.x != 0.f) | (v.y != 0.f) | (v.z != 0.f) | (v.w != 0.f);
    }
    int any_k = 0;
    const uint4* k4 = (const uint4*)kpm;
    for (int i = idx; i < (BB * SS) / 16; i += stride) {
        uint4 v = __ldg(k4 + i);
        any_k |= ((v.x | v.y | v.z | v.w) != 0u);
    }
    if (__any_sync(0xffffffffu, any_m) && (threadIdx.x & 31) == 0)
        atomicOr(&g_flags, 1);
    if (__any_sync(0xffffffffu, any_k) && (threadIdx.x & 31) == 0)
        atomicOr(&g_flags, 2);
}

// ---------------------------------------------------------------------------
// Tensor-core GEMM (unchanged, validated): bf16x3 split emulation.
// ---------------------------------------------------------------------------
#define TILE_B (128 * 144)
#define GEMM_SMEM_BYTES (4 * TILE_B)

__device__ __forceinline__ void cvt_split_store(char* hi_tile, char* lo_tile,
                                                int r, int kq, float4 a) {
    u32 a0 = __float_as_uint(a.x), a1 = __float_as_uint(a.y);
    u32 a2 = __float_as_uint(a.z), a3 = __float_as_uint(a.w);
    u32 h01, h23;
    asm("prmt.b32 %0,%1,%2,0x7632;" : "=r"(h01) : "r"(a0), "r"(a1));
    asm("prmt.b32 %0,%1,%2,0x7632;" : "=r"(h23) : "r"(a2), "r"(a3));
    float l0 = a.x - __uint_as_float(a0 & 0xffff0000u);
    float l1 = a.y - __uint_as_float(a1 & 0xffff0000u);
    float l2 = a.z - __uint_as_float(a2 & 0xffff0000u);
    float l3 = a.w - __uint_as_float(a3 & 0xffff0000u);
    u32 lo01, lo23;
    asm("cvt.rn.bf16x2.f32 %0,%1,%2;" : "=r"(lo01) : "f"(l1), "f"(l0));
    asm("cvt.rn.bf16x2.f32 %0,%1,%2;" : "=r"(lo23) : "f"(l3), "f"(l2));
    u32 boff = (u32)(r * 144 + kq * 2);
    *(uint2*)(hi_tile + boff) = make_uint2(h01, h23);
    *(uint2*)(lo_tile + boff) = make_uint2(lo01, lo23);
}

template <int MODE>
__global__ __launch_bounds__(256, 2) void tc_gemm(
    const float* __restrict__ A, const float* __restrict__ W,
    const float* __restrict__ bias, float* __restrict__ out,
    int M, int N, int K)
{
    extern __shared__ __align__(128) char dsm[];
    char* Ahi = dsm;
    char* Alo = dsm + TILE_B;
    char* Bhi = dsm + 2 * TILE_B;
    char* Blo = dsm + 3 * TILE_B;
    const u32 sbase = smem_u32(dsm);

    const int tid = threadIdx.x;
    const int lane = tid & 31;
    const int wid = tid >> 5;
    const int wm = wid & 3;
    const int wn = wid >> 2;
    const int bm = blockIdx.y * 128, bn = blockIdx.x * 128;

    const u32 aOff = (u32)((wm * 32 + (lane & 15)) * 144 + (lane >> 4) * 16);
    const u32 bRow = (u32)(((lane >> 4) << 3) + (lane & 7));
    const u32 bOff = (u32)((wn * 64 + bRow) * 144 + ((lane >> 3) & 1) * 16);

    float acc[2][8][4];
#pragma unroll
    for (int i = 0; i < 2; i++)
#pragma unroll
        for (int j = 0; j < 8; j++)
#pragma unroll
            for (int q = 0; q < 4; q++) acc[i][j][q] = 0.f;

    const float* Ap = A + (size_t)bm * K;
    const float* Wp = W + (size_t)bn * K;

    const int nchunk = K / 64;
    for (int c = 0; c < nchunk; c++) {
        const int k0 = c * 64;
#pragma unroll
        for (int i = 0; i < 8; i++) {
            int f = tid + i * 256;
            int r = f >> 4, kq = (f & 15) << 2;
            float4 a = __ldg((const float4*)(Ap + (size_t)r * K + k0 + kq));
            cvt_split_store(Ahi, Alo, r, kq, a);
            float4 w = __ldg((const float4*)(Wp + (size_t)r * K + k0 + kq));
            cvt_split_store(Bhi, Blo, r, kq, w);
        }
        __syncthreads();

        const u32 aHiA = sbase + aOff;
        const u32 aLoA = aHiA + TILE_B;
        const u32 bHiA = sbase + 2 * TILE_B + bOff;
        const u32 bLoA = bHiA + TILE_B;
#pragma unroll
        for (int ks = 0; ks < 4; ks++) {
            u32 ah[2][4], al[2][4];
#pragma unroll
            for (int mf = 0; mf < 2; mf++) {
                ldsm4(aHiA + mf * 2304 + ks * 32, ah[mf][0], ah[mf][1], ah[mf][2], ah[mf][3]);
                ldsm4(aLoA + mf * 2304 + ks * 32, al[mf][0], al[mf][1], al[mf][2], al[mf][3]);
            }
#pragma unroll
            for (int ng = 0; ng < 4; ng++) {
                u32 bh[4], bl[4];
                ldsm4(bHiA + ng * 2304 + ks * 32, bh[0], bh[1], bh[2], bh[3]);
                ldsm4(bLoA + ng * 2304 + ks * 32, bl[0], bl[1], bl[2], bl[3]);
#pragma unroll
                for (int half = 0; half < 2; half++) {
                    const u32* bhp = &bh[half * 2];
                    const u32* blp = &bl[half * 2];
                    int nf = ng * 2 + half;
#pragma unroll
                    for (int mf = 0; mf < 2; mf++) {
                        mma16816(acc[mf][nf], ah[mf], bhp);
                        mma16816(acc[mf][nf], ah[mf], blp);
                        mma16816(acc[mf][nf], al[mf], bhp);
                    }
                }
            }
        }
        __syncthreads();
    }

#pragma unroll
    for (int mf = 0; mf < 2; mf++) {
#pragma unroll
        for (int nf = 0; nf < 8; nf++) {
            int m = bm + wm * 32 + mf * 16 + (lane >> 2);
            int n = bn + wn * 64 + nf * 8 + (lane & 3) * 2;
            float b0 = __ldg(bias + n), b1 = __ldg(bias + n + 1);
            float2 v0 = make_float2(acc[mf][nf][0] + b0, acc[mf][nf][1] + b1);
            float2 v1 = make_float2(acc[mf][nf][2] + b0, acc[mf][nf][3] + b1);
            if (MODE == 0) {
                *(float2*)(out + (size_t)m * N + n) = v0;
                *(float2*)(out + (size_t)(m + 8) * N + n) = v1;
            } else {
                int h = n >> 6, d = n & (DD - 1);
                int b_ = m >> 11, t = m & (TT - 1);
                size_t idx0 = (((size_t)b_ * HH + h) * TT + t) * DD + d;
                *(float2*)(out + idx0) = v0;
                int m1 = m + 8;
                int b1_ = m1 >> 11, t1 = m1 & (TT - 1);
                size_t idx1 = (((size_t)b1_ * HH + h) * TT + t1) * DD + d;
                *(float2*)(out + idx1) = v1;
            }
        }
    }
}

// ---------------------------------------------------------------------------
// Tensor-core flash attention.
// Q pre-scaled by SCALE (exact pow2) during split. P kept f16-hi only (2-MMA PV).
// Mask / key-padding paths gated by g_flags (fast path: both zero).
// smem layout (byte offsets, row stride 144B = 72 f16):
//   0      Qhi[128][72]   18432
//   18432  Qlo            18432
//   36864  Khi[64][72]     9216
//   46080  Klo             9216
//   55296  Vhi[64][72]     9216
//   64512  Vlo             9216
//   73728  kpms[2048] f32  8192
#define ATTN_SMEM_BYTES 81920
#define QLO_D 18432
#define KH_O 36864
#define KLO_D 9216
#define VH_O 55296
#define VLO_D 9216
#define KPM_O 73728

__device__ __forceinline__ void split_store_f16(char* hi_t, char* lo_t,
                                                int r, int kq, float4 a) {
    u32 h01 = f16pair(a.x, a.y);
    u32 h23 = f16pair(a.z, a.w);
    float bx, by, bz, bw;
    h2unpack(h01, bx, by);
    h2unpack(h23, bz, bw);
    u32 l01 = f16pair(a.x - bx, a.y - by);
    u32 l23 = f16pair(a.z - bz, a.w - bw);
    u32 off = (u32)(r * 144 + kq * 2);
    *(uint2*)(hi_t + off) = make_uint2(h01, h23);
    *(uint2*)(lo_t + off) = make_uint2(l01, l23);
}

__global__ __launch_bounds__(256, 2) void attn_tc(
    const float* __restrict__ mask, const unsigned char* __restrict__ kpm)
{
    extern __shared__ __align__(128) char smr[];
    float* kpms = (float*)(smr + KPM_O);
    const u32 sb = smem_u32(smr);

    const int tid = threadIdx.x;
    const int lane = tid & 31;
    const int w = tid >> 5;
    const int tblk = blockIdx.x * 128;
    const int h = blockIdx.y, b = blockIdx.z;
    const float NEGINF = __int_as_float(0xff800000);

    const int flags = g_flags;
    const bool mflag = (flags & 1) != 0;
    const bool kflag = (flags & 2) != 0;

    const size_t baseq = (((size_t)b * HH + h) * TT + tblk) * DD;
    const size_t basekv = ((size_t)b * HH + h) * (size_t)SS * DD;

    // Load + split Q tile (128 x 64), folding in SCALE (exact: 2^-3)
#pragma unroll
    for (int i = 0; i < 8; i++) {
        int f = tid + i * 256;
        int r = f >> 4, kq = (f & 15) << 2;
        float4 v = *(const float4*)(g_q + baseq + (size_t)r * DD + kq);
        v.x *= SCALE_F; v.y *= SCALE_F; v.z *= SCALE_F; v.w *= SCALE_F;
        split_store_f16(smr, smr + QLO_D, r, kq, v);
    }
    if (kflag) {
#pragma unroll
        for (int i = 0; i < 8; i++) {
            int s = tid + i * 256;
            kpms[s] = kpm[(size_t)b * SS + s] ? NEGINF : 0.f;
        }
    }

    const u32 aQ = sb + (u32)((w * 16 + (lane & 15)) * 144 + (lane >> 4) * 16);
    const u32 bK = sb + KH_O + (u32)((((lane >> 4) << 3) + (lane & 7)) * 144 +
                                     ((lane >> 3) & 1) * 16);
    const u32 bV = sb + VH_O + (u32)((lane & 15) * 144 + (lane >> 4) * 16);

    const int row0 = tblk + w * 16 + (lane >> 2);
    const float* mrow0 = mask + (size_t)row0 * SS;
    const float* mrow1 = mrow0 + 8 * (size_t)SS;

    float O[8][4];
#pragma unroll
    for (int i = 0; i < 8; i++)
#pragma unroll
        for (int j = 0; j < 4; j++) O[i][j] = 0.f;
    float l0 = 0.f, l1 = 0.f, m0 = NEGINF, m1 = NEGINF;

    for (int s0 = 0; s0 < SS; s0 += 64) {
        __syncthreads();
#pragma unroll
        for (int i = 0; i < 4; i++) {
            int f = tid + i * 256;
            int s = f >> 4, dg = (f & 15) << 2;
            float4 kv = *(const float4*)(g_k + basekv + (size_t)(s0 + s) * DD + dg);
            split_store_f16(smr + KH_O, smr + KH_O + KLO_D, s, dg, kv);
            float4 vv = *(const float4*)(g_v + basekv + (size_t)(s0 + s) * DD + dg);
            split_store_f16(smr + VH_O, smr + VH_O + VLO_D, s, dg, vv);
        }
        __syncthreads();

        // S = Q K^T  (f16 3-term split, scale pre-folded into Q)
        float sacc[8][4];
#pragma unroll
        for (int i = 0; i < 8; i++)
#pragma unroll
            for (int j = 0; j < 4; j++) sacc[i][j] = 0.f;
#pragma unroll
        for (int ks = 0; ks < 4; ks++) {
            u32 ah[4], al[4];
            ldsm4(aQ + ks * 32, ah[0], ah[1], ah[2], ah[3]);
            ldsm4(aQ + QLO_D + ks * 32, al[0], al[1], al[2], al[3]);
#pragma unroll
            for (int sg = 0; sg < 4; sg++) {
                u32 bh[4], bl[4];
                ldsm4(bK + sg * 2304 + ks * 32, bh[0], bh[1], bh[2], bh[3]);
                ldsm4(bK + KLO_D + sg * 2304 + ks * 32, bl[0], bl[1], bl[2], bl[3]);
#pragma unroll
                for (int half = 0; half < 2; half++) {
                    float* c = sacc[sg * 2 + half];
                    mma16816h(c, ah, &bh[half * 2]);
                    mma16816h(c, ah, &bl[half * 2]);
                    mma16816h(c, al, &bh[half * 2]);
                }
            }
        }

        // optional mask / key-padding adds (gated; fast path skips)
        if (kflag) {
#pragma unroll
            for (int nf = 0; nf < 8; nf++) {
                int col = s0 + nf * 8 + (lane & 3) * 2;
                float2 kp = *(const float2*)&kpms[col];
                sacc[nf][0] += kp.x; sacc[nf][1] += kp.y;
                sacc[nf][2] += kp.x; sacc[nf][3] += kp.y;
            }
        }
        if (mflag) {
#pragma unroll
            for (int nf = 0; nf < 8; nf++) {
                int col = s0 + nf * 8 + (lane & 3) * 2;
                float2 mv0 = __ldg((const float2*)(mrow0 + col));
                float2 mv1 = __ldg((const float2*)(mrow1 + col));
                sacc[nf][0] += mv0.x; sacc[nf][1] += mv0.y;
                sacc[nf][2] += mv1.x; sacc[nf][3] += mv1.y;
            }
        }

        // row max
        float cm0 = NEGINF, cm1 = NEGINF;
#pragma unroll
        for (int nf = 0; nf < 8; nf++) {
            cm0 = fmaxf(cm0, fmaxf(sacc[nf][0], sacc[nf][1]));
            cm1 = fmaxf(cm1, fmaxf(sacc[nf][2], sacc[nf][3]));
        }
        cm0 = fmaxf(cm0, __shfl_xor_sync(0xffffffffu, cm0, 1));
        cm0 = fmaxf(cm0, __shfl_xor_sync(0xffffffffu, cm0, 2));
        cm1 = fmaxf(cm1, __shfl_xor_sync(0xffffffffu, cm1, 1));
        cm1 = fmaxf(cm1, __shfl_xor_sync(0xffffffffu, cm1, 2));

        float mn0 = fmaxf(m0, cm0), mn1 = fmaxf(m1, cm1);
        float c0 = __expf(m0 - mn0), c1 = __expf(m1 - mn1);
        m0 = mn0; m1 = mn1;
        l0 *= c0; l1 *= c1;
#pragma unroll
        for (int nf = 0; nf < 8; nf++) {
            O[nf][0] *= c0; O[nf][1] *= c0;
            O[nf][2] *= c1; O[nf][3] *= c1;
        }

        // p = exp(s - m) (fp32), keep f16-hi fragments only
        u32 phi[8][2];
        float rs0 = 0.f, rs1 = 0.f;
#pragma unroll
        for (int nf = 0; nf < 8; nf++) {
            float p0 = __expf(sacc[nf][0] - mn0);
            float p1 = __expf(sacc[nf][1] - mn0);
            float p2 = __expf(sacc[nf][2] - mn1);
            float p3 = __expf(sacc[nf][3] - mn1);
            rs0 += p0 + p1; rs1 += p2 + p3;
            phi[nf][0] = f16pair(p0, p1);
            phi[nf][1] = f16pair(p2, p3);
        }
        rs0 += __shfl_xor_sync(0xffffffffu, rs0, 1);
        rs0 += __shfl_xor_sync(0xffffffffu, rs0, 2);
        rs1 += __shfl_xor_sync(0xffffffffu, rs1, 1);
        rs1 += __shfl_xor_sync(0xffffffffu, rs1, 2);
        l0 += rs0; l1 += rs1;

        // O += P V  (P-hi x (V-hi + V-lo): 2 MMAs per fragment)
#pragma unroll
        for (int ks = 0; ks < 4; ks++) {
            u32 ah[4] = {phi[2 * ks][0], phi[2 * ks][1],
                         phi[2 * ks + 1][0], phi[2 * ks + 1][1]};
#pragma unroll
            for (int dg = 0; dg < 4; dg++) {
                u32 bh[4], bl[4];
                ldsm4t(bV + ks * 2304 + dg * 32, bh[0], bh[1], bh[2], bh[3]);
                ldsm4t(bV + VLO_D + ks * 2304 + dg * 32, bl[0], bl[1], bl[2], bl[3]);
                mma16816h(O[dg * 2], ah, &bh[0]);
                mma16816h(O[dg * 2], ah, &bl[0]);
                mma16816h(O[dg * 2 + 1], ah, &bh[2]);
                mma16816h(O[dg * 2 + 1], ah, &bl[2]);
            }
        }
    }

    // epilogue
    float i0 = __fdividef(1.f, l0), i1 = __fdividef(1.f, l1);
    float* op0 = g_attn + ((size_t)b * TT + row0) * CC + h * DD + (lane & 3) * 2;
    float* op1 = op0 + 8 * (size_t)CC;
#pragma unroll
    for (int nf = 0; nf < 8; nf++) {
        *(float2*)(op0 + nf * 8) = make_float2(O[nf][0] * i0, O[nf][1] * i0);
        *(float2*)(op1 + nf * 8) = make_float2(O[nf][2] * i1, O[nf][3] * i1);
    }
}

// ---------------------------------------------------------------------------
// Launch
// ---------------------------------------------------------------------------
extern "C" void kernel_launch(void* const* d_in, const int* in_sizes, int n_in,
                              void* d_out, int out_size)
{
    (void)in_sizes; (void)n_in; (void)out_size;
    const float* query = (const float*)d_in[0];
    const float* key   = (const float*)d_in[1];
    const float* value = (const float*)d_in[2];
    const float* mask  = (const float*)d_in[3];
    const unsigned char* kpm = (const unsigned char*)d_in[4];
    const float* Wq = (const float*)d_in[5];
    const float* bq = (const float*)d_in[6];
    const float* Wk = (const float*)d_in[7];
    const float* bk = (const float*)d_in[8];
    const float* Wv = (const float*)d_in[9];
    const float* bv = (const float*)d_in[10];
    const float* Wout = (const float*)d_in[11];
    const float* bout = (const float*)d_in[12];
    float* out = (float*)d_out;

    float *qp, *kp, *vp, *ap;
    cudaGetSymbolAddress((void**)&qp, g_q);
    cudaGetSymbolAddress((void**)&kp, g_k);
    cudaGetSymbolAddress((void**)&vp, g_v);
    cudaGetSymbolAddress((void**)&ap, g_attn);
    int* fp;
    cudaGetSymbolAddress((void**)&fp, g_flags);

    cudaFuncSetAttribute(tc_gemm<0>, cudaFuncAttributeMaxDynamicSharedMemorySize,
                         GEMM_SMEM_BYTES);
    cudaFuncSetAttribute(tc_gemm<1>, cudaFuncAttributeMaxDynamicSharedMemorySize,
                         GEMM_SMEM_BYTES);
    cudaFuncSetAttribute(attn_tc, cudaFuncAttributeMaxDynamicSharedMemorySize,
                         ATTN_SMEM_BYTES);

    cudaMemsetAsync(fp, 0, sizeof(int));
    mask_check<<<1024, 256>>>(mask, kpm);

    dim3 ggrid(CC / 128, (BB * TT) / 128);   // (8, 64)
    tc_gemm<1><<<ggrid, 256, GEMM_SMEM_BYTES>>>(query, Wq, bq, qp, BB * TT, CC, CC);
    tc_gemm<1><<<ggrid, 256, GEMM_SMEM_BYTES>>>(key,   Wk, bk, kp, BB * SS, CC, CC);
    tc_gemm<1><<<ggrid, 256, GEMM_SMEM_BYTES>>>(value, Wv, bv, vp, BB * SS, CC, CC);

    attn_tc<<<dim3(TT / 128, HH, BB), 256, ATTN_SMEM_BYTES>>>(mask, kpm);

    tc_gemm<0><<<ggrid, 256, GEMM_SMEM_BYTES>>>(ap, Wout, bout, out, BB * TT, CC, CC);
}